// round 11
// baseline (speedup 1.0000x reference)
#include <cuda_runtime.h>
#include <cuda_bf16.h>

#define S_LEN 6
#define E_DIM 256
#define NH    8
#define HD    32
#define HW    4096   // 64*64
#define B_MAX 16
#define BSE   (B_MAX * S_LEN * E_DIM)
#define SE    (S_LEN * E_DIM)            // 1536 slices per batch

// Scratch (no cudaMalloc allowed)
__device__ float g_buf[BSE];
__device__ float q_buf[BSE];
__device__ float k_buf[BSE];
__device__ float v_buf[BSE];
__device__ float og_buf[BSE];

// -------------------------------------------------------------------------
// Kernel 1: global spatial mean over 64x64 + temporal_pos -> g[b,s,e]
// Chunked: covers slices [base, base + gridDim.x)
// -------------------------------------------------------------------------
__global__ void __launch_bounds__(256) pool_kernel(
    const float* __restrict__ ff, const float* __restrict__ tpos, int base)
{
    int idx = base + blockIdx.x;          // global slice: b*S*E + s*E + e
    const float4* p = reinterpret_cast<const float4*>(ff + (size_t)idx * HW);

    float sum = 0.f;
#pragma unroll
    for (int i = 0; i < 4; i++) {
        float4 v = __ldcs(&p[threadIdx.x + i * 256]);
        sum += (v.x + v.y) + (v.z + v.w);
    }
#pragma unroll
    for (int off = 16; off > 0; off >>= 1)
        sum += __shfl_xor_sync(0xFFFFFFFFu, sum, off);

    __shared__ float wsum[8];
    int lane = threadIdx.x & 31, wid = threadIdx.x >> 5;
    if (lane == 0) wsum[wid] = sum;
    __syncthreads();
    if (threadIdx.x == 0) {
        float tot = 0.f;
#pragma unroll
        for (int w = 0; w < 8; w++) tot += wsum[w];
        g_buf[idx] = tot * (1.0f / HW) + tpos[idx % SE];
    }
}

// -------------------------------------------------------------------------
// Kernel 2: QKV. block = (b,s) x quarter of 768 rows; bs = bs_base + blk>>2
// -------------------------------------------------------------------------
__global__ void __launch_bounds__(256) qkv_kernel(
    const float* __restrict__ Wq, const float* __restrict__ bq,
    const float* __restrict__ Wk, const float* __restrict__ bk,
    const float* __restrict__ Wv, const float* __restrict__ bv,
    int bs_base)
{
    int bs = bs_base + (blockIdx.x >> 2);
    int quarter = blockIdx.x & 3;
    int tid = threadIdx.x;
    __shared__ float sg[E_DIM];
    sg[tid] = g_buf[bs * E_DIM + tid];
    __syncthreads();

    int warp = tid >> 5, lane = tid & 31;
    const float4* gv = reinterpret_cast<const float4*>(sg);
    float4 g0 = gv[lane];
    float4 g1 = gv[lane + 32];

    int row_lo = quarter * 192;
    int row_hi = row_lo + 192;
#pragma unroll 1
    for (int base = row_lo + warp * 4; base < row_hi; base += 32) {
        float acc[4];
#pragma unroll
        for (int rr = 0; rr < 4; rr++) {
            int r = base + rr;
            int which = r >> 8;
            int e = r & 255;
            const float* W = (which == 0) ? Wq : (which == 1) ? Wk : Wv;
            const float4* wrow = reinterpret_cast<const float4*>(W + e * E_DIM);
            float4 w0 = wrow[lane];
            float4 w1 = wrow[lane + 32];
            acc[rr] = w0.x * g0.x + w0.y * g0.y + w0.z * g0.z + w0.w * g0.w
                    + w1.x * g1.x + w1.y * g1.y + w1.z * g1.z + w1.w * g1.w;
        }
#pragma unroll
        for (int off = 16; off > 0; off >>= 1) {
#pragma unroll
            for (int rr = 0; rr < 4; rr++)
                acc[rr] += __shfl_xor_sync(0xFFFFFFFFu, acc[rr], off);
        }
        if (lane < 4) {
            int r = base + lane;
            int which = r >> 8;
            int e = r & 255;
            const float* bias = (which == 0) ? bq : (which == 1) ? bk : bv;
            float* dst = (which == 0) ? q_buf : (which == 1) ? k_buf : v_buf;
            dst[bs * E_DIM + e] = acc[lane] + bias[e];
        }
    }
}

// -------------------------------------------------------------------------
// Kernel 3: fused softmax + AV + output projection.
// block = (b,s) x quarter of the 256 Wo rows; bs = bs_base + blk>>2
// -------------------------------------------------------------------------
__global__ void __launch_bounds__(256) attnproj_kernel(
    const float* __restrict__ Wo, const float* __restrict__ bo,
    float* __restrict__ attn_out, int write_attn, int bs_base)
{
    int bs = bs_base + (blockIdx.x >> 2);
    int quarter = blockIdx.x & 3;
    int b = bs / S_LEN, s = bs % S_LEN;
    int tid = threadIdx.x;

    __shared__ float sq[E_DIM];
    __shared__ float sk[S_LEN][E_DIM];
    __shared__ float sv[S_LEN][E_DIM];
    __shared__ float sc[NH][S_LEN];
    __shared__ float sat[E_DIM];

    sq[tid] = q_buf[bs * E_DIM + tid];
    for (int i = tid; i < S_LEN * E_DIM; i += 256) {
        sk[i / E_DIM][i % E_DIM] = k_buf[b * S_LEN * E_DIM + i];
        sv[i / E_DIM][i % E_DIM] = v_buf[b * S_LEN * E_DIM + i];
    }
    __syncthreads();

    if (tid < NH) {
        int h = tid;
        float row[S_LEN];
        const float scale = 0.17677669529663687f;  // 1/sqrt(32)
        float mx = -1e30f;
        for (int t = 0; t <= s; t++) {
            float d = 0.f;
#pragma unroll
            for (int j = 0; j < HD; j++)
                d += sq[h * HD + j] * sk[t][h * HD + j];
            d *= scale;
            row[t] = d;
            mx = fmaxf(mx, d);
        }
        float den = 0.f;
        for (int t = 0; t <= s; t++) { row[t] = __expf(row[t] - mx); den += row[t]; }
        float inv = 1.f / den;
#pragma unroll
        for (int t = 0; t < S_LEN; t++)
            sc[h][t] = (t <= s) ? row[t] * inv : 0.f;
    }
    __syncthreads();

    if (write_attn && quarter == 0 && tid < NH * S_LEN) {
        int h = tid / S_LEN, t = tid % S_LEN;
        attn_out[((b * NH + h) * S_LEN + s) * S_LEN + t] = sc[h][t];
    }

    {
        int e = tid, h = e / HD;
        float a = 0.f;
        for (int t = 0; t <= s; t++)
            a += sc[h][t] * sv[t][e];
        sat[e] = a;
    }
    __syncthreads();

    int warp = tid >> 5, lane = tid & 31;
    const float4* av = reinterpret_cast<const float4*>(sat);
    float4 a0 = av[lane];
    float4 a1 = av[lane + 32];

    int row_lo = quarter * 64;
    int row_hi = row_lo + 64;
#pragma unroll 1
    for (int base = row_lo + warp * 4; base < row_hi; base += 32) {
        float acc[4];
#pragma unroll
        for (int rr = 0; rr < 4; rr++) {
            int e = base + rr;
            const float4* wrow = reinterpret_cast<const float4*>(Wo + e * E_DIM);
            float4 w0 = wrow[lane];
            float4 w1 = wrow[lane + 32];
            acc[rr] = w0.x * a0.x + w0.y * a0.y + w0.z * a0.z + w0.w * a0.w
                    + w1.x * a1.x + w1.y * a1.y + w1.z * a1.z + w1.w * a1.w;
        }
#pragma unroll
        for (int off = 16; off > 0; off >>= 1) {
#pragma unroll
            for (int rr = 0; rr < 4; rr++)
                acc[rr] += __shfl_xor_sync(0xFFFFFFFFu, acc[rr], off);
        }
        if (lane < 4) {
            int e = base + lane;
            og_buf[bs * E_DIM + e] = acc[lane] + bo[e];
        }
    }
}

// -------------------------------------------------------------------------
// Kernel 4: cross = ff + og broadcast. Chunked by base slice.
// -------------------------------------------------------------------------
__global__ void __launch_bounds__(256) add_kernel(
    const float* __restrict__ ff, float* __restrict__ out, int base)
{
    int idx = base + blockIdx.x;
    float add = og_buf[idx];
    const float4* p = reinterpret_cast<const float4*>(ff + (size_t)idx * HW);
    float4* o = reinterpret_cast<float4*>(out + (size_t)idx * HW);
#pragma unroll
    for (int i = 0; i < 4; i++) {
        float4 v = __ldcs(&p[threadIdx.x + i * 256]);
        v.x += add; v.y += add; v.z += add; v.w += add;
        __stcs(&o[threadIdx.x + i * 256], v);
    }
}

extern "C" void kernel_launch(void* const* d_in, const int* in_sizes, int n_in,
                              void* d_out, int out_size)
{
    const float* ff   = (const float*)d_in[0];
    const float* Wq   = (const float*)d_in[1];
    const float* bq   = (const float*)d_in[2];
    const float* Wk   = (const float*)d_in[3];
    const float* bk   = (const float*)d_in[4];
    const float* Wv   = (const float*)d_in[5];
    const float* bv   = (const float*)d_in[6];
    const float* Wo   = (const float*)d_in[7];
    const float* bo   = (const float*)d_in[8];
    const float* tpos = (const float*)d_in[9];

    int ff_elems = in_sizes[0];                       // B*S*E*H*W
    int B = ff_elems / (S_LEN * E_DIM * HW);          // 16
    float* cross = (float*)d_out;
    int attn_elems = B * NH * S_LEN * S_LEN;
    int write_attn = (out_size >= ff_elems + attn_elems) ? 1 : 0;
    float* attn_out = cross + ff_elems;

    // chunking: 4 chunks of B/4 batches (fallback: 1 chunk)
    int chb = (B % 4 == 0 && B >= 4 && B <= 64) ? B / 4 : B;
    int nch = B / chb;
    if (nch > 16) { chb = B; nch = 1; }
    int chunk_slices = chb * SE;

    static cudaStream_t ms = nullptr;
    static cudaEvent_t evP[16], evM[16];
    if (ms == nullptr) {
        cudaStreamCreateWithFlags(&ms, cudaStreamNonBlocking);
        for (int i = 0; i < 16; i++) {
            cudaEventCreateWithFlags(&evP[i], cudaEventDisableTiming);
            cudaEventCreateWithFlags(&evM[i], cudaEventDisableTiming);
        }
    }

    // Phase A: pools stream back-to-back on main stream; event per chunk
    for (int c = 0; c < nch; c++) {
        pool_kernel<<<chunk_slices, 256>>>(ff, tpos, c * chunk_slices);
        cudaEventRecord(evP[c], 0);
    }
    // Phase B: middles on forked stream, overlapped with remaining streaming
    for (int c = 0; c < nch; c++) {
        cudaStreamWaitEvent(ms, evP[c], 0);
        qkv_kernel<<<chb * S_LEN * 4, 256, 0, ms>>>(Wq, bq, Wk, bk, Wv, bv,
                                                    c * chb * S_LEN);
        attnproj_kernel<<<chb * S_LEN * 4, 256, 0, ms>>>(Wo, bo, attn_out,
                                                         write_attn,
                                                         c * chb * S_LEN);
        cudaEventRecord(evM[c], ms);
    }
    // Phase C: adds stream back-to-back on main stream, each gated on its middle
    for (int c = 0; c < nch; c++) {
        cudaStreamWaitEvent((cudaStream_t)0, evM[c], 0);
        add_kernel<<<chunk_slices, 256>>>(ff, cross, c * chunk_slices);
    }
}